// round 1
// baseline (speedup 1.0000x reference)
#include <cuda_runtime.h>
#include <cstdint>

typedef unsigned long long u64;

// ---------------- packed f32x2 helpers (Blackwell FFMA2 path) ----------------
__device__ __forceinline__ u64 pk2(float a, float b) {
    u64 r; asm("mov.b64 %0, {%1,%2};" : "=l"(r) : "f"(a), "f"(b)); return r;
}
__device__ __forceinline__ void upk2(u64 v, float& a, float& b) {
    asm("mov.b64 {%0,%1}, %2;" : "=f"(a), "=f"(b) : "l"(v));
}
__device__ __forceinline__ u64 ffma2(u64 a, u64 b, u64 c) {
    u64 d; asm("fma.rn.f32x2 %0, %1, %2, %3;" : "=l"(d) : "l"(a), "l"(b), "l"(c)); return d;
}
__device__ __forceinline__ u64 fmul2(u64 a, u64 b) {
    u64 d; asm("mul.rn.f32x2 %0, %1, %2;" : "=l"(d) : "l"(a), "l"(b)); return d;
}
__device__ __forceinline__ u64 fadd2(u64 a, u64 b) {
    u64 d; asm("add.rn.f32x2 %0, %1, %2;" : "=l"(d) : "l"(a), "l"(b)); return d;
}

__device__ __forceinline__ float sigmoidf_(float x) {
    // fast sigmoid: EX2-based exp + fast rcp; ~2 ulp, way inside 1e-3 budget
    return __fdividef(1.0f, 1.0f + __expf(-x));
}

#define H    1024
#define DIN  784
#define DOUT 10
#define MAXB 16384

// scratch for x@W1 (constant across settle steps). 64 MB static __device__ array
// (allocation-free per harness rules).
__device__ float g_xW1[(size_t)MAXB * H];

// ==================== Kernel 1: g_xW1 = x @ W1 (fp32, packed FFMA2) ====================
// 128x128 block tile, BK=16, 256 threads, 8x8 microtile per thread (4+4 split layout),
// B-pairs packed into f32x2 so each FFMA2 does 2 MACs.
__global__ __launch_bounds__(256) void gemm_xw1(const float* __restrict__ A,
                                                const float* __restrict__ Bm) {
    __shared__ float As[16][136];   // A transposed [k][m], padded to kill store conflicts
    __shared__ float Bs[16][128];   // [k][n]

    const int tid = threadIdx.x;
    const int tx = tid & 15, ty = tid >> 4;
    const int bm0 = blockIdx.y * 128;
    const int bn0 = blockIdx.x * 128;

    u64 cc[8][4];
#pragma unroll
    for (int i = 0; i < 8; ++i)
#pragma unroll
        for (int p = 0; p < 4; ++p) cc[i][p] = 0ULL;

    const float* Ap = A + (size_t)bm0 * DIN;
    const float* Bp = Bm + bn0;

    for (int k0 = 0; k0 < DIN; k0 += 16) {
#pragma unroll
        for (int l = 0; l < 2; ++l) {
            int idx = tid + l * 256;
            int ar = idx >> 2;
            int ac = (idx & 3) << 2;
            float4 v = *(const float4*)(Ap + (size_t)ar * DIN + k0 + ac);
            As[ac + 0][ar] = v.x; As[ac + 1][ar] = v.y;
            As[ac + 2][ar] = v.z; As[ac + 3][ar] = v.w;
            int br = idx >> 5;
            int bc = (idx & 31) << 2;
            *(float4*)&Bs[br][bc] = *(const float4*)(Bp + (size_t)(k0 + br) * H + bc);
        }
        __syncthreads();
#pragma unroll
        for (int k = 0; k < 16; ++k) {
            float4 a0 = *(const float4*)&As[k][ty * 4];
            float4 a1 = *(const float4*)&As[k][64 + ty * 4];
            float4 b0 = *(const float4*)&Bs[k][tx * 4];
            float4 b1 = *(const float4*)&Bs[k][64 + tx * 4];
            u64 bp[4] = {pk2(b0.x, b0.y), pk2(b0.z, b0.w),
                         pk2(b1.x, b1.y), pk2(b1.z, b1.w)};
            float av[8] = {a0.x, a0.y, a0.z, a0.w, a1.x, a1.y, a1.z, a1.w};
#pragma unroll
            for (int i = 0; i < 8; ++i) {
                u64 a2 = pk2(av[i], av[i]);
#pragma unroll
                for (int p = 0; p < 4; ++p) cc[i][p] = ffma2(a2, bp[p], cc[i][p]);
            }
        }
        __syncthreads();
    }

    float* Cp = g_xW1 + (size_t)bm0 * H + bn0;
#pragma unroll
    for (int i = 0; i < 8; ++i) {
        int m = (i < 4) ? (ty * 4 + i) : (64 + ty * 4 + (i - 4));
        float o0, o1, o2, o3;
        upk2(cc[i][0], o0, o1); upk2(cc[i][1], o2, o3);
        *(float4*)(Cp + (size_t)m * H + tx * 4) = make_float4(o0, o1, o2, o3);
        upk2(cc[i][2], o0, o1); upk2(cc[i][3], o2, o3);
        *(float4*)(Cp + (size_t)m * H + 64 + tx * 4) = make_float4(o0, o1, o2, o3);
    }
}

// ==================== Kernel 2: 50-step settle, fully on-chip ====================
// Each CTA owns R=4 batch rows. Per thread: 4 h-columns (h = tid + 256*j), so
// u1 lives in 16 registers/thread and the W2 rows it needs (4 x 10) live in 20
// packed registers — both W2 dot products per step run out of registers.
// xW1 slab (4x1024) cached in SMEM once. u2/r2 (10 per row) in SMEM.
// Per-step global memory traffic: zero.
__global__ __launch_bounds__(256, 2) void settle_kernel(
    const float* __restrict__ u1g, const float* __restrict__ u2g,
    const float* __restrict__ W2g, const float* __restrict__ b1g,
    const float* __restrict__ b2g, const int* __restrict__ steps_p,
    float* __restrict__ outg)
{
    __shared__ float xw1_s[4 * H];
    __shared__ __align__(16) float r2_s[4][12];
    __shared__ __align__(16) float u2_s[4][12];
    __shared__ __align__(16) float wpart[4][32][12];

    const int tid  = threadIdx.x;
    const int lane = tid & 31;
    const int wid  = tid >> 5;
    const int b0   = blockIdx.x * 4;
    const int nsteps = *steps_p;

    // W2 rows (packed over output pairs) + b1 for this thread's 4 h columns
    u64 w2p[4][5];
    float b1j[4];
#pragma unroll
    for (int j = 0; j < 4; ++j) {
        int h = tid + 256 * j;
        const float* w = W2g + h * DOUT;
#pragma unroll
        for (int k = 0; k < 5; ++k) w2p[j][k] = pk2(w[2 * k], w[2 * k + 1]);
        b1j[j] = b1g[h];
    }

    // u1 state in registers
    float u1v[4][4];
#pragma unroll
    for (int r = 0; r < 4; ++r)
#pragma unroll
        for (int j = 0; j < 4; ++j)
            u1v[r][j] = u1g[(size_t)(b0 + r) * H + tid + 256 * j];

    // xW1 slab -> SMEM (once)
    {
        const float4* src = (const float4*)(g_xW1 + (size_t)b0 * H);
        float4* dst = (float4*)xw1_s;
#pragma unroll
        for (int i = 0; i < 4; ++i) dst[tid + 256 * i] = src[tid + 256 * i];
    }

    const int r_u2 = tid / 10;
    const int o_u2 = tid - r_u2 * 10;      // valid for tid < 40
    float b2v = 0.0f;
    if (tid < 40) {
        u2_s[r_u2][o_u2] = u2g[(b0 + r_u2) * DOUT + o_u2];
        b2v = b2g[o_u2];
    }
    __syncthreads();

    for (int s = 0; s < nsteps; ++s) {
        // --- phase 1: r2 = sigmoid(u2) (old u2) ---
        if (tid < 40) r2_s[r_u2][o_u2] = sigmoidf_(u2_s[r_u2][o_u2]);
        __syncthreads();

        // --- phase 2: u1 update + partial r1@W2 ---
#pragma unroll
        for (int r = 0; r < 4; ++r) {
            u64 r2p[5];
            {
                const float4* rp = (const float4*)&r2_s[r][0];
                float4 q0 = rp[0];
                float4 q1 = rp[1];
                float2 q2 = *(const float2*)&r2_s[r][8];
                r2p[0] = pk2(q0.x, q0.y); r2p[1] = pk2(q0.z, q0.w);
                r2p[2] = pk2(q1.x, q1.y); r2p[3] = pk2(q1.z, q1.w);
                r2p[4] = pk2(q2.x, q2.y);
            }
            u64 qacc[5] = {0ULL, 0ULL, 0ULL, 0ULL, 0ULL};
#pragma unroll
            for (int j = 0; j < 4; ++j) {
                float u  = u1v[r][j];
                float sg = sigmoidf_(u);                 // r1 (old u1)
                // p = sum_o r2[o] * W2[h][o]  (packed dot, 5 FFMA2)
                u64 p2 = fmul2(w2p[j][0], r2p[0]);
                p2 = ffma2(w2p[j][1], r2p[1], p2);
                p2 = ffma2(w2p[j][2], r2p[2], p2);
                p2 = ffma2(w2p[j][3], r2p[3], p2);
                p2 = ffma2(w2p[j][4], r2p[4], p2);
                float pa, pb; upk2(p2, pa, pb);
                // q[o] += r1 * W2[h][o]  (packed, 5 FFMA2)
                u64 s2 = pk2(sg, sg);
#pragma unroll
                for (int k = 0; k < 5; ++k) qacc[k] = ffma2(s2, w2p[j][k], qacc[k]);
                // u1' = 0.5*u1 + 0.5*d1*(0.5*xW1 + p + b1)
                float xw = xw1_s[r * H + tid + 256 * j];
                float d  = sg - sg * sg;
                float t  = fmaf(0.5f, xw, (pa + pb) + b1j[j]);
                u1v[r][j] = fmaf(0.5f * d, t, 0.5f * u);
            }
            // 3-stage butterfly: lanes 0..3 hold disjoint partial sums
#pragma unroll
            for (int off = 16; off >= 4; off >>= 1)
#pragma unroll
                for (int k = 0; k < 5; ++k)
                    qacc[k] = fadd2(qacc[k], __shfl_xor_sync(0xffffffffu, qacc[k], off));
            if (lane < 4) {
                float* wp = &wpart[r][wid * 4 + lane][0];
#pragma unroll
                for (int k = 0; k < 5; ++k) {
                    float qa, qb; upk2(qacc[k], qa, qb);
                    *(float2*)(wp + 2 * k) = make_float2(qa, qb);
                }
            }
        }
        __syncthreads();

        // --- phase 3: u2' = 0.5*u2 + 0.5*d2*(q + b2) ---
        if (tid < 40) {
            float q = 0.0f;
#pragma unroll
            for (int w = 0; w < 32; ++w) q += wpart[r_u2][w][o_u2];
            float r2v = r2_s[r_u2][o_u2];
            float d2  = r2v - r2v * r2v;
            u2_s[r_u2][o_u2] = fmaf(0.5f * d2, q + b2v, 0.5f * u2_s[r_u2][o_u2]);
        }
        __syncthreads();
    }

    if (tid < 40)
        outg[(b0 + r_u2) * DOUT + o_u2] = sigmoidf_(u2_s[r_u2][o_u2]);
}

// ==================== launch ====================
extern "C" void kernel_launch(void* const* d_in, const int* in_sizes, int n_in,
                              void* d_out, int out_size) {
    const float* x     = (const float*)d_in[0];
    const float* u1    = (const float*)d_in[1];
    const float* u2    = (const float*)d_in[2];
    const float* W1    = (const float*)d_in[3];
    const float* W2    = (const float*)d_in[4];
    const float* b1    = (const float*)d_in[5];
    const float* b2    = (const float*)d_in[6];
    const int*   steps = (const int*)d_in[7];
    float* out = (float*)d_out;

    const int B = in_sizes[1] / H;          // u1 is [B, H]

    dim3 ggrid(H / 128, B / 128);
    gemm_xw1<<<ggrid, 256>>>(x, W1);
    settle_kernel<<<B / 4, 256>>>(u1, u2, W2, b1, b2, steps, out);
}

// round 2
// speedup vs baseline: 1.0962x; 1.0962x over previous
#include <cuda_runtime.h>
#include <cstdint>

typedef unsigned long long u64;

// ---------------- packed f32x2 helpers ----------------
__device__ __forceinline__ u64 pk2(float a, float b) {
    u64 r; asm("mov.b64 %0, {%1,%2};" : "=l"(r) : "f"(a), "f"(b)); return r;
}
__device__ __forceinline__ void upk2(u64 v, float& a, float& b) {
    asm("mov.b64 {%0,%1}, %2;" : "=f"(a), "=f"(b) : "l"(v));
}
__device__ __forceinline__ u64 ffma2(u64 a, u64 b, u64 c) {
    u64 d; asm("fma.rn.f32x2 %0, %1, %2, %3;" : "=l"(d) : "l"(a), "l"(b), "l"(c)); return d;
}
__device__ __forceinline__ u64 fmul2(u64 a, u64 b) {
    u64 d; asm("mul.rn.f32x2 %0, %1, %2;" : "=l"(d) : "l"(a), "l"(b)); return d;
}
__device__ __forceinline__ u64 fadd2(u64 a, u64 b) {
    u64 d; asm("add.rn.f32x2 %0, %1, %2;" : "=l"(d) : "l"(a), "l"(b)); return d;
}
// sigmoid via MUFU.TANH: sigma(u) = 0.5*tanh(0.5u) + 0.5   (1 MUFU + 2 fma-pipe)
__device__ __forceinline__ float sig_tanh(float u) {
    float th;
    asm("tanh.approx.f32 %0, %1;" : "=f"(th) : "f"(0.5f * u));
    return fmaf(0.5f, th, 0.5f);
}

#define H    1024
#define DIN  784
#define DOUT 10
#define MAXB 16384

// scratch for x@W1 (loop-invariant). static __device__ (allocation-free).
__device__ float g_xW1[(size_t)MAXB * H];

// ==================== Kernel 1: g_xW1 = x @ W1 (fp32 FFMA2, double-buffered) ====================
__global__ __launch_bounds__(256) void gemm_xw1(const float* __restrict__ A,
                                                const float* __restrict__ Bm) {
    __shared__ float As[16][136];   // [k][m] transposed, padded
    __shared__ float Bs[16][128];   // [k][n]

    const int tid = threadIdx.x;
    const int tx = tid & 15, ty = tid >> 4;
    const int bm0 = blockIdx.y * 128;
    const int bn0 = blockIdx.x * 128;

    u64 cc[8][4];
#pragma unroll
    for (int i = 0; i < 8; ++i)
#pragma unroll
        for (int p = 0; p < 4; ++p) cc[i][p] = 0ULL;

    const float* Ap = A + (size_t)bm0 * DIN;
    const float* Bp = Bm + bn0;

    // per-thread load coordinates (2 chunks)
    int ar[2], ac[2], br[2], bc[2];
#pragma unroll
    for (int l = 0; l < 2; ++l) {
        int idx = tid + l * 256;
        ar[l] = idx >> 2;  ac[l] = (idx & 3) << 2;
        br[l] = idx >> 5;  bc[l] = (idx & 31) << 2;
    }

    float4 rva[2], rvb[2];
#pragma unroll
    for (int l = 0; l < 2; ++l) {
        rva[l] = *(const float4*)(Ap + (size_t)ar[l] * DIN + 0 + ac[l]);
        rvb[l] = *(const float4*)(Bp + (size_t)(0 + br[l]) * H + bc[l]);
    }

    for (int k0 = 0; k0 < DIN; k0 += 16) {
#pragma unroll
        for (int l = 0; l < 2; ++l) {
            As[ac[l] + 0][ar[l]] = rva[l].x; As[ac[l] + 1][ar[l]] = rva[l].y;
            As[ac[l] + 2][ar[l]] = rva[l].z; As[ac[l] + 3][ar[l]] = rva[l].w;
            *(float4*)&Bs[br[l]][bc[l]] = rvb[l];
        }
        __syncthreads();

        int kn = k0 + 16;
        if (kn < DIN) {
#pragma unroll
            for (int l = 0; l < 2; ++l) {
                rva[l] = *(const float4*)(Ap + (size_t)ar[l] * DIN + kn + ac[l]);
                rvb[l] = *(const float4*)(Bp + (size_t)(kn + br[l]) * H + bc[l]);
            }
        }

#pragma unroll
        for (int k = 0; k < 16; ++k) {
            float4 a0 = *(const float4*)&As[k][ty * 4];
            float4 a1 = *(const float4*)&As[k][64 + ty * 4];
            float4 b0 = *(const float4*)&Bs[k][tx * 4];
            float4 b1 = *(const float4*)&Bs[k][64 + tx * 4];
            u64 bp[4] = {pk2(b0.x, b0.y), pk2(b0.z, b0.w),
                         pk2(b1.x, b1.y), pk2(b1.z, b1.w)};
            float av[8] = {a0.x, a0.y, a0.z, a0.w, a1.x, a1.y, a1.z, a1.w};
#pragma unroll
            for (int i = 0; i < 8; ++i) {
                u64 a2 = pk2(av[i], av[i]);
#pragma unroll
                for (int p = 0; p < 4; ++p) cc[i][p] = ffma2(a2, bp[p], cc[i][p]);
            }
        }
        __syncthreads();
    }

    float* Cp = g_xW1 + (size_t)bm0 * H + bn0;
#pragma unroll
    for (int i = 0; i < 8; ++i) {
        int m = (i < 4) ? (ty * 4 + i) : (64 + ty * 4 + (i - 4));
        float o0, o1, o2, o3;
        upk2(cc[i][0], o0, o1); upk2(cc[i][1], o2, o3);
        *(float4*)(Cp + (size_t)m * H + tx * 4) = make_float4(o0, o1, o2, o3);
        upk2(cc[i][2], o0, o1); upk2(cc[i][3], o2, o3);
        *(float4*)(Cp + (size_t)m * H + 64 + tx * 4) = make_float4(o0, o1, o2, o3);
    }
}

// ==================== Kernel 2: 50-step settle (2 barriers/step) ====================
// CTA = 256 threads, 4 batch rows. Thread owns h in {tid + 256j : j=0..3}, W2 rows
// in registers (packed), u1 in registers, c1 = 0.5*xW1 + b1 in SMEM (precomputed once).
// Per step:
//   phase A (all 256): u1 update + per-thread q partials, 2-level xor butterfly,
//                      lanes 0-7 store 8 partials/warp (64 total) to wpart (transposed).
//   phase B (80 thr) : 2 threads per (row,out) sum 32 partials each (LDS.128),
//                      pair-combine via shfl, update u2 (registers), emit r2 to SMEM.
__global__ __launch_bounds__(256, 2) void settle_kernel(
    const float* __restrict__ u1g, const float* __restrict__ u2g,
    const float* __restrict__ W2g, const float* __restrict__ b1g,
    const float* __restrict__ b2g, const int* __restrict__ steps_p,
    float* __restrict__ outg)
{
    __shared__ float c1_s[4 * H];                 // 0.5*xW1 + b1
    __shared__ __align__(16) float r2_s[4][12];   // pairs 8B-aligned (stride 48B)
    __shared__ __align__(16) float wpart[4 * 10 * 68];  // [r][o][64+4pad]

    const int tid  = threadIdx.x;
    const int lane = tid & 31;
    const int wid  = tid >> 5;
    const int b0   = blockIdx.x * 4;
    const int nsteps = *steps_p;

    // ---- per-thread constants: W2 rows (packed) ----
    u64 w2p[4][5];
#pragma unroll
    for (int j = 0; j < 4; ++j) {
        const float* w = W2g + (tid + 256 * j) * DOUT;
#pragma unroll
        for (int k = 0; k < 5; ++k) w2p[j][k] = pk2(w[2 * k], w[2 * k + 1]);
    }

    // ---- u1 state in registers ----
    float u1v[4][4];
#pragma unroll
    for (int r = 0; r < 4; ++r)
#pragma unroll
        for (int j = 0; j < 4; ++j)
            u1v[r][j] = u1g[(size_t)(b0 + r) * H + tid + 256 * j];

    // ---- c1 = 0.5*xW1 + b1 -> SMEM (once) ----
    {
        const float4* xs = (const float4*)(g_xW1 + (size_t)b0 * H);
        const float4* bs = (const float4*)b1g;
        float4* dst = (float4*)c1_s;
#pragma unroll
        for (int i = 0; i < 4; ++i) {
            int e = tid + 256 * i;                 // float4 index within 4*1024
            float4 xv = xs[e];
            float4 bv = bs[e & 255];               // b1 repeats per row (256 float4 = 1024 f)
            dst[e] = make_float4(fmaf(0.5f, xv.x, bv.x), fmaf(0.5f, xv.y, bv.y),
                                 fmaf(0.5f, xv.z, bv.z), fmaf(0.5f, xv.w, bv.w));
        }
    }

    // ---- phase-B thread setup: 2 threads per (r,o); u2 lives in registers ----
    const bool pb_act = tid < 80;
    const unsigned pb_mask = (tid < 64) ? 0xffffffffu : 0x0000ffffu;
    const int idx40 = tid >> 1;              // 0..39
    const int half  = tid & 1;
    const int r_b   = idx40 / DOUT;
    const int o_b   = idx40 - r_b * DOUT;
    float u2v = 0.0f, b2v = 0.0f, r2v = 0.0f;
    const float* wp_rd = &wpart[(r_b * DOUT + o_b) * 68 + half * 32];
    if (pb_act) {
        u2v = u2g[(b0 + r_b) * DOUT + o_b];
        b2v = b2g[o_b];
        r2v = sig_tanh(u2v);
        if (!half) r2_s[r_b][o_b] = r2v;
    }
    __syncthreads();

    for (int s = 0; s < nsteps; ++s) {
        // ---------- phase A ----------
#pragma unroll
        for (int r = 0; r < 4; ++r) {
            u64 r2p[5];
#pragma unroll
            for (int k = 0; k < 5; ++k)
                r2p[k] = *(const u64*)&r2_s[r][2 * k];      // broadcast LDS.64

            u64 qacc[5] = {0ULL, 0ULL, 0ULL, 0ULL, 0ULL};
#pragma unroll
            for (int j = 0; j < 4; ++j) {
                float u  = u1v[r][j];
                float sg = sig_tanh(u);                      // r1
                // p = W2[h] . r2  (5 FFMA2)
                u64 p2 = fmul2(w2p[j][0], r2p[0]);
                p2 = ffma2(w2p[j][1], r2p[1], p2);
                p2 = ffma2(w2p[j][2], r2p[2], p2);
                p2 = ffma2(w2p[j][3], r2p[3], p2);
                p2 = ffma2(w2p[j][4], r2p[4], p2);
                float pa, pb; upk2(p2, pa, pb);
                // q[o] += r1 * W2[h][o]
                u64 s2 = pk2(sg, sg);
#pragma unroll
                for (int k = 0; k < 5; ++k) qacc[k] = ffma2(s2, w2p[j][k], qacc[k]);
                // u1' = 0.5*(u + d1*(c1 + p))
                float t = c1_s[r * H + tid + 256 * j] + (pa + pb);
                float d = fmaf(-sg, sg, sg);
                u1v[r][j] = 0.5f * fmaf(d, t, u);
            }
            // 2-level butterfly: groups of 4 lanes (stride 8)
#pragma unroll
            for (int off = 16; off >= 8; off >>= 1)
#pragma unroll
                for (int k = 0; k < 5; ++k)
                    qacc[k] = fadd2(qacc[k], __shfl_xor_sync(0xffffffffu, qacc[k], off));
            if (lane < 8) {
                float* wp = &wpart[r * DOUT * 68 + wid * 8 + lane];
#pragma unroll
                for (int k = 0; k < 5; ++k) {
                    float qa, qb; upk2(qacc[k], qa, qb);
                    wp[(2 * k)     * 68] = qa;
                    wp[(2 * k + 1) * 68] = qb;
                }
            }
        }
        __syncthreads();

        // ---------- phase B ----------
        if (pb_act) {
            const float4* pv = (const float4*)wp_rd;
            float4 a0 = pv[0], a1 = pv[1], a2 = pv[2], a3 = pv[3];
            float4 a4 = pv[4], a5 = pv[5], a6 = pv[6], a7 = pv[7];
            float4 sA = make_float4(a0.x + a4.x, a0.y + a4.y, a0.z + a4.z, a0.w + a4.w);
            float4 sB = make_float4(a1.x + a5.x, a1.y + a5.y, a1.z + a5.z, a1.w + a5.w);
            float4 sC = make_float4(a2.x + a6.x, a2.y + a6.y, a2.z + a6.z, a2.w + a6.w);
            float4 sD = make_float4(a3.x + a7.x, a3.y + a7.y, a3.z + a7.z, a3.w + a7.w);
            float q = ((sA.x + sA.y) + (sA.z + sA.w)) + ((sB.x + sB.y) + (sB.z + sB.w))
                    + ((sC.x + sC.y) + (sC.z + sC.w)) + ((sD.x + sD.y) + (sD.z + sD.w));
            q += __shfl_xor_sync(pb_mask, q, 1);
            float d2 = fmaf(-r2v, r2v, r2v);
            u2v = 0.5f * fmaf(d2, q + b2v, u2v);     // u2' = 0.5*(u2 + d2*(q+b2))
            r2v = sig_tanh(u2v);
            if (!half) r2_s[r_b][o_b] = r2v;
        }
        __syncthreads();
    }

    if (pb_act && !half)
        outg[(b0 + r_b) * DOUT + o_b] = r2v;          // y = sigmoid(u2_final)
}

// ==================== launch ====================
extern "C" void kernel_launch(void* const* d_in, const int* in_sizes, int n_in,
                              void* d_out, int out_size) {
    const float* x     = (const float*)d_in[0];
    const float* u1    = (const float*)d_in[1];
    const float* u2    = (const float*)d_in[2];
    const float* W1    = (const float*)d_in[3];
    const float* W2    = (const float*)d_in[4];
    const float* b1    = (const float*)d_in[5];
    const float* b2    = (const float*)d_in[6];
    const int*   steps = (const int*)d_in[7];
    float* out = (float*)d_out;

    const int B = in_sizes[1] / H;          // u1 is [B, H]

    dim3 ggrid(H / 128, B / 128);
    gemm_xw1<<<ggrid, 256>>>(x, W1);
    settle_kernel<<<B / 4, 256>>>(u1, u2, W2, b1, b2, steps, out);
}

// round 3
// speedup vs baseline: 1.1364x; 1.0366x over previous
#include <cuda_runtime.h>
#include <cstdint>

typedef unsigned long long u64;

// ---------------- packed f32x2 helpers ----------------
__device__ __forceinline__ u64 pk2(float a, float b) {
    u64 r; asm("mov.b64 %0, {%1,%2};" : "=l"(r) : "f"(a), "f"(b)); return r;
}
__device__ __forceinline__ void upk2(u64 v, float& a, float& b) {
    asm("mov.b64 {%0,%1}, %2;" : "=f"(a), "=f"(b) : "l"(v));
}
__device__ __forceinline__ u64 ffma2(u64 a, u64 b, u64 c) {
    u64 d; asm("fma.rn.f32x2 %0, %1, %2, %3;" : "=l"(d) : "l"(a), "l"(b), "l"(c)); return d;
}
__device__ __forceinline__ u64 fmul2(u64 a, u64 b) {
    u64 d; asm("mul.rn.f32x2 %0, %1, %2;" : "=l"(d) : "l"(a), "l"(b)); return d;
}
__device__ __forceinline__ u64 fadd2(u64 a, u64 b) {
    u64 d; asm("add.rn.f32x2 %0, %1, %2;" : "=l"(d) : "l"(a), "l"(b)); return d;
}
__device__ __forceinline__ float tanh_(float x) {
    float t; asm("tanh.approx.f32 %0, %1;" : "=f"(t) : "f"(x)); return t;
}

#define H    1024
#define DIN  784
#define DOUT 10
#define MAXB 16384

__device__ float g_xW1[(size_t)MAXB * H];   // x @ W1 scratch (loop-invariant)

// ==================== Kernel 1: g_xW1 = x @ W1 ====================
// A stored in SMEM pre-duplicated as u64 (a,a): a-fragments are ready FFMA2
// operands (no per-k MOV duplication). 128x128 tile, BK=16, 8x8 microtile.
__global__ __launch_bounds__(256, 2) void gemm_xw1(const float* __restrict__ A,
                                                   const float* __restrict__ Bm) {
    __shared__ u64   As2[16][130];   // [k][m] duplicated pairs; 130 = 2 mod 16 (bank-balanced)
    __shared__ float Bs[16][128];    // [k][n]

    const int tid = threadIdx.x;
    const int tx = tid & 15, ty = tid >> 4;
    const int bm0 = blockIdx.y * 128;
    const int bn0 = blockIdx.x * 128;

    u64 cc[8][4];
#pragma unroll
    for (int i = 0; i < 8; ++i)
#pragma unroll
        for (int p = 0; p < 4; ++p) cc[i][p] = 0ULL;

    const float* Ap = A + (size_t)bm0 * DIN;
    const float* Bp = Bm + bn0;

    int ar[2], ac[2], br[2], bc[2];
#pragma unroll
    for (int l = 0; l < 2; ++l) {
        int idx = tid + l * 256;
        ar[l] = idx >> 2;  ac[l] = (idx & 3) << 2;
        br[l] = idx >> 5;  bc[l] = (idx & 31) << 2;
    }

    float4 rva[2], rvb[2];
#pragma unroll
    for (int l = 0; l < 2; ++l) {
        rva[l] = *(const float4*)(Ap + (size_t)ar[l] * DIN + ac[l]);
        rvb[l] = *(const float4*)(Bp + (size_t)br[l] * H + bc[l]);
    }

    for (int k0 = 0; k0 < DIN; k0 += 16) {
#pragma unroll
        for (int l = 0; l < 2; ++l) {
            As2[ac[l] + 0][ar[l]] = pk2(rva[l].x, rva[l].x);
            As2[ac[l] + 1][ar[l]] = pk2(rva[l].y, rva[l].y);
            As2[ac[l] + 2][ar[l]] = pk2(rva[l].z, rva[l].z);
            As2[ac[l] + 3][ar[l]] = pk2(rva[l].w, rva[l].w);
            *(float4*)&Bs[br[l]][bc[l]] = rvb[l];
        }
        __syncthreads();

        int kn = k0 + 16;
        if (kn < DIN) {
#pragma unroll
            for (int l = 0; l < 2; ++l) {
                rva[l] = *(const float4*)(Ap + (size_t)ar[l] * DIN + kn + ac[l]);
                rvb[l] = *(const float4*)(Bp + (size_t)(kn + br[l]) * H + bc[l]);
            }
        }

#pragma unroll
        for (int k = 0; k < 16; ++k) {
            ulonglong2 a01 = *(const ulonglong2*)&As2[k][ty * 4];
            ulonglong2 a23 = *(const ulonglong2*)&As2[k][ty * 4 + 2];
            ulonglong2 a45 = *(const ulonglong2*)&As2[k][64 + ty * 4];
            ulonglong2 a67 = *(const ulonglong2*)&As2[k][64 + ty * 4 + 2];
            float4 b0 = *(const float4*)&Bs[k][tx * 4];
            float4 b1 = *(const float4*)&Bs[k][64 + tx * 4];
            u64 bp[4] = {pk2(b0.x, b0.y), pk2(b0.z, b0.w),
                         pk2(b1.x, b1.y), pk2(b1.z, b1.w)};
            u64 av[8] = {a01.x, a01.y, a23.x, a23.y, a45.x, a45.y, a67.x, a67.y};
#pragma unroll
            for (int i = 0; i < 8; ++i)
#pragma unroll
                for (int p = 0; p < 4; ++p) cc[i][p] = ffma2(av[i], bp[p], cc[i][p]);
        }
        __syncthreads();
    }

    float* Cp = g_xW1 + (size_t)bm0 * H + bn0;
#pragma unroll
    for (int i = 0; i < 8; ++i) {
        int m = (i < 4) ? (ty * 4 + i) : (64 + ty * 4 + (i - 4));
        float o0, o1, o2, o3;
        upk2(cc[i][0], o0, o1); upk2(cc[i][1], o2, o3);
        *(float4*)(Cp + (size_t)m * H + tx * 4) = make_float4(o0, o1, o2, o3);
        upk2(cc[i][2], o0, o1); upk2(cc[i][3], o2, o3);
        *(float4*)(Cp + (size_t)m * H + 64 + tx * 4) = make_float4(o0, o1, o2, o3);
    }
}

// ==================== Kernel 2: 50-step settle ====================
// State v = u1/2 (so tanh needs no pre-multiply). 1/16 scale folded into the
// register-resident W2 copy and into c1 = (xW1/2 + b1)/16. q accumulates
// S' = sum th*W2/16; the r1 = (1+th)/2 constant half folds into C2 = colsum/2 + b2.
// 1-level butterfly (5 SHFL.64), lanes 0-15 store pairs; phase B: 160 threads,
// 4 per (row,out), conflict-free stride-33 u64 partial layout.
__global__ __launch_bounds__(256, 2) void settle_kernel(
    const float* __restrict__ u1g, const float* __restrict__ u2g,
    const float* __restrict__ W2g, const float* __restrict__ b1g,
    const float* __restrict__ b2g, const int* __restrict__ steps_p,
    float* __restrict__ outg)
{
    __shared__ float c1_s[4 * H];                 // (0.5*xW1 + b1)/16
    __shared__ __align__(16) float r2_s[4][12];
    __shared__ u64 wpart[80 * 33];                // [n'][pos], n' = (r*5+k)*4+q4

    const int tid  = threadIdx.x;
    const int lane = tid & 31;
    const int wid  = tid >> 5;
    const int b0   = blockIdx.x * 4;
    const int nsteps = *steps_p;

    // ---- W2/16 rows (packed) in registers ----
    u64 w2p[4][5];
#pragma unroll
    for (int j = 0; j < 4; ++j) {
        const float* w = W2g + (tid + 256 * j) * DOUT;
#pragma unroll
        for (int k = 0; k < 5; ++k)
            w2p[j][k] = pk2(w[2 * k] * 0.0625f, w[2 * k + 1] * 0.0625f);
    }

    // ---- state v = u1/2 in registers ----
    float u1v[4][4];
#pragma unroll
    for (int r = 0; r < 4; ++r)
#pragma unroll
        for (int j = 0; j < 4; ++j)
            u1v[r][j] = 0.5f * u1g[(size_t)(b0 + r) * H + tid + 256 * j];

    // ---- c1 = (0.5*xW1 + b1)/16 -> SMEM ----
    {
        const float4* xs = (const float4*)(g_xW1 + (size_t)b0 * H);
        const float4* bs = (const float4*)b1g;
        float4* dst = (float4*)c1_s;
#pragma unroll
        for (int i = 0; i < 4; ++i) {
            int e = tid + 256 * i;
            float4 xv = xs[e];
            float4 bv = bs[e & 255];
            dst[e] = make_float4(fmaf(0.03125f, xv.x, 0.0625f * bv.x),
                                 fmaf(0.03125f, xv.y, 0.0625f * bv.y),
                                 fmaf(0.03125f, xv.z, 0.0625f * bv.z),
                                 fmaf(0.03125f, xv.w, 0.0625f * bv.w));
        }
    }

    // ---- phase-B thread mapping: 160 threads, 4 per (r,o) ----
    const bool pb = tid < 160;
    const int r_b  = tid / 40;
    const int rem  = tid - 40 * r_b;
    const int o_b  = rem >> 2;
    const int q4   = rem & 3;
    const int k_b  = o_b >> 1;
    const int half = o_b & 1;
    const float* fb = (const float*)(wpart + ((size_t)((r_b * 5 + k_b) * 4 + q4)) * 33);
    const float* fb_pre = (const float*)(wpart + ((size_t)(k_b * 4 + q4)) * 33);

    // ---- pre-pass: colsum(W2)/16 via the same reduction path (r=0 slots) ----
    {
        u64 qa[5];
#pragma unroll
        for (int k = 0; k < 5; ++k)
            qa[k] = fadd2(fadd2(w2p[0][k], w2p[1][k]), fadd2(w2p[2][k], w2p[3][k]));
#pragma unroll
        for (int k = 0; k < 5; ++k)
            qa[k] = fadd2(qa[k], __shfl_xor_sync(0xffffffffu, qa[k], 16));
        if (lane < 16) {
            int pIdx = wid * 16 + lane;
            int chunk = pIdx >> 5, pos = pIdx & 31;
#pragma unroll
            for (int k = 0; k < 5; ++k)
                wpart[(k * 4 + chunk) * 33 + pos] = qa[k];
        }
    }
    __syncthreads();

    float C2v = 0.0f, wv = 0.0f, r2v = 0.0f;
    if (pb) {
        float s0a = 0, s0b = 0, s1a = 0, s1b = 0;
#pragma unroll
        for (int i = 0; i < 16; ++i) {
            float2 za = *(const float2*)(fb_pre + 4 * i);
            float2 zb = *(const float2*)(fb_pre + 4 * i + 2);
            s0a += za.x; s1a += za.y; s0b += zb.x; s1b += zb.y;
        }
        float s = half ? (s1a + s1b) : (s0a + s0b);
        s += __shfl_xor_sync(0xffffffffu, s, 1);
        s += __shfl_xor_sync(0xffffffffu, s, 2);
        C2v = fmaf(8.0f, s, b2g[o_b]);             // colsum/2 + b2
        wv  = 0.5f * u2g[(b0 + r_b) * DOUT + o_b]; // u2/2
        float tau = tanh_(wv);
        r2v = fmaf(0.5f, tau, 0.5f);
        if (q4 == 0) r2_s[r_b][o_b] = r2v;
    }
    __syncthreads();

    for (int s = 0; s < nsteps; ++s) {
        // ---------- phase A ----------
#pragma unroll
        for (int r = 0; r < 4; ++r) {
            ulonglong2 ra = *(const ulonglong2*)&r2_s[r][0];
            ulonglong2 rb = *(const ulonglong2*)&r2_s[r][4];
            u64 rc = *(const u64*)&r2_s[r][8];
            u64 r2p[5] = {ra.x, ra.y, rb.x, rb.y, rc};
            u64 qacc[5] = {0ULL, 0ULL, 0ULL, 0ULL, 0ULL};
#pragma unroll
            for (int j = 0; j < 4; ++j) {
                float v  = u1v[r][j];
                float th = tanh_(v);
                u64 p2 = fmul2(w2p[j][0], r2p[0]);
                p2 = ffma2(w2p[j][1], r2p[1], p2);
                p2 = ffma2(w2p[j][2], r2p[2], p2);
                p2 = ffma2(w2p[j][3], r2p[3], p2);
                p2 = ffma2(w2p[j][4], r2p[4], p2);
                float pa, pb2; upk2(p2, pa, pb2);
                u64 th2 = pk2(th, th);
#pragma unroll
                for (int k = 0; k < 5; ++k) qacc[k] = ffma2(th2, w2p[j][k], qacc[k]);
                float t   = (pa + pb2) + c1_s[r * H + tid + 256 * j];
                float omt = fmaf(-th, th, 1.0f);
                u1v[r][j] = fmaf(omt, t, 0.5f * v);   // v' = v/2 + (1-th^2)*t
            }
            // 1-level butterfly; lanes 0-15 hold pair-partials pIdx = wid*16+lane
#pragma unroll
            for (int k = 0; k < 5; ++k)
                qacc[k] = fadd2(qacc[k], __shfl_xor_sync(0xffffffffu, qacc[k], 16));
            if (lane < 16) {
                int pIdx = wid * 16 + lane;
                int chunk = pIdx >> 5, pos = pIdx & 31;
#pragma unroll
                for (int k = 0; k < 5; ++k)
                    wpart[((r * 5 + k) * 4 + chunk) * 33 + pos] = qacc[k];
            }
        }
        __syncthreads();

        // ---------- phase B ----------
        if (pb) {
            float s0a = 0, s0b = 0, s1a = 0, s1b = 0;
#pragma unroll
            for (int i = 0; i < 16; ++i) {
                float2 za = *(const float2*)(fb + 4 * i);
                float2 zb = *(const float2*)(fb + 4 * i + 2);
                s0a += za.x; s1a += za.y; s0b += zb.x; s1b += zb.y;
            }
            float sv = half ? (s1a + s1b) : (s0a + s0b);
            sv += __shfl_xor_sync(0xffffffffu, sv, 1);
            sv += __shfl_xor_sync(0xffffffffu, sv, 2);
            float gq  = fmaf(8.0f, sv, C2v);          // q + b2
            float tau = tanh_(wv);
            float om  = fmaf(-tau, tau, 1.0f);
            wv = fmaf(0.0625f * om, gq, 0.5f * wv);   // w' = w/2 + (1-tau^2)(q+b2)/16
            r2v = fmaf(0.5f, tanh_(wv), 0.5f);
            if (q4 == 0) r2_s[r_b][o_b] = r2v;
        }
        __syncthreads();
    }

    if (pb && q4 == 0)
        outg[(b0 + r_b) * DOUT + o_b] = r2v;          // y = sigmoid(u2_final)
}

// ==================== launch ====================
extern "C" void kernel_launch(void* const* d_in, const int* in_sizes, int n_in,
                              void* d_out, int out_size) {
    const float* x     = (const float*)d_in[0];
    const float* u1    = (const float*)d_in[1];
    const float* u2    = (const float*)d_in[2];
    const float* W1    = (const float*)d_in[3];
    const float* W2    = (const float*)d_in[4];
    const float* b1    = (const float*)d_in[5];
    const float* b2    = (const float*)d_in[6];
    const int*   steps = (const int*)d_in[7];
    float* out = (float*)d_out;

    const int B = in_sizes[1] / H;

    dim3 ggrid(H / 128, B / 128);
    gemm_xw1<<<ggrid, 256>>>(x, W1);
    settle_kernel<<<B / 4, 256>>>(u1, u2, W2, b1, b2, steps, out);
}

// round 5
// speedup vs baseline: 1.2952x; 1.1398x over previous
#include <cuda_runtime.h>
#include <cuda_bf16.h>
#include <mma.h>
#include <cstdint>

using namespace nvcuda;

typedef unsigned long long u64;

// ---------------- packed f32x2 helpers ----------------
__device__ __forceinline__ u64 pk2(float a, float b) {
    u64 r; asm("mov.b64 %0, {%1,%2};" : "=l"(r) : "f"(a), "f"(b)); return r;
}
__device__ __forceinline__ void upk2(u64 v, float& a, float& b) {
    asm("mov.b64 {%0,%1}, %2;" : "=f"(a), "=f"(b) : "l"(v));
}
__device__ __forceinline__ u64 ffma2(u64 a, u64 b, u64 c) {
    u64 d; asm("fma.rn.f32x2 %0, %1, %2, %3;" : "=l"(d) : "l"(a), "l"(b), "l"(c)); return d;
}
__device__ __forceinline__ u64 fmul2(u64 a, u64 b) {
    u64 d; asm("mul.rn.f32x2 %0, %1, %2;" : "=l"(d) : "l"(a), "l"(b)); return d;
}
__device__ __forceinline__ u64 fadd2(u64 a, u64 b) {
    u64 d; asm("add.rn.f32x2 %0, %1, %2;" : "=l"(d) : "l"(a), "l"(b)); return d;
}
__device__ __forceinline__ float tanh_(float x) {
    float t; asm("tanh.approx.f32 %0, %1;" : "=f"(t) : "f"(x)); return t;
}

#define H    1024
#define DIN  784
#define DOUT 10
#define MAXB 16384
#define KPAD 832          // 784 padded to multiple of 64; rows stay 16B-aligned

__device__ float g_xW1[(size_t)MAXB * H];                        // x @ W1 (fp32)
__device__ __align__(16) __nv_bfloat16 g_xh[(size_t)MAXB * KPAD];
__device__ __align__(16) __nv_bfloat16 g_xl[(size_t)MAXB * KPAD];
__device__ __align__(16) __nv_bfloat16 g_wh[(size_t)H * KPAD];   // W1^T hi  [n][k]
__device__ __align__(16) __nv_bfloat16 g_wl[(size_t)H * KPAD];   // W1^T lo  [n][k]

// ==================== conversion kernels ====================
__global__ __launch_bounds__(256) void conv_x(const float* __restrict__ x, int B) {
    int u = blockIdx.x * 256 + threadIdx.x;
    if (u >= B * 208) return;                 // 208 = KPAD/4 float4-units per row
    int m = u / 208, ku = u - m * 208;
    ushort4 hh = {0, 0, 0, 0}, ll = {0, 0, 0, 0};
    if (ku < 196) {                           // 784/4 real units
        float4 v = *(const float4*)(x + (size_t)m * DIN + ku * 4);
        __nv_bfloat16 h0 = __float2bfloat16(v.x), h1 = __float2bfloat16(v.y);
        __nv_bfloat16 h2 = __float2bfloat16(v.z), h3 = __float2bfloat16(v.w);
        __nv_bfloat16 l0 = __float2bfloat16(v.x - __bfloat162float(h0));
        __nv_bfloat16 l1 = __float2bfloat16(v.y - __bfloat162float(h1));
        __nv_bfloat16 l2 = __float2bfloat16(v.z - __bfloat162float(h2));
        __nv_bfloat16 l3 = __float2bfloat16(v.w - __bfloat162float(h3));
        hh = make_ushort4(__bfloat16_as_ushort(h0), __bfloat16_as_ushort(h1),
                          __bfloat16_as_ushort(h2), __bfloat16_as_ushort(h3));
        ll = make_ushort4(__bfloat16_as_ushort(l0), __bfloat16_as_ushort(l1),
                          __bfloat16_as_ushort(l2), __bfloat16_as_ushort(l3));
    }
    *(ushort4*)(g_xh + (size_t)m * KPAD + ku * 4) = hh;
    *(ushort4*)(g_xl + (size_t)m * KPAD + ku * 4) = ll;
}

__global__ __launch_bounds__(256) void conv_w1t(const float* __restrict__ W1) {
    int u = blockIdx.x * 256 + threadIdx.x;
    if (u >= H * KPAD) return;
    int n = u / KPAD, k = u - n * KPAD;
    __nv_bfloat16 h = __ushort_as_bfloat16(0), l = __ushort_as_bfloat16(0);
    if (k < DIN) {
        float w = W1[(size_t)k * H + n];
        h = __float2bfloat16(w);
        l = __float2bfloat16(w - __bfloat162float(h));
    }
    g_wh[(size_t)n * KPAD + k] = h;
    g_wl[(size_t)n * KPAD + k] = l;
}

// ==================== split-bf16 mma.sync GEMM: g_xW1 = x @ W1 ====================
// Base-target tensor cores (wmma -> mma.sync HMMA; no tcgen05/TMA on sm_100 base).
// CTA tile 128x128, 8 warps in 2x4 -> warp tile 64x32. K-step 16, 49 steps.
// acc += Ah*Bh + Ah*Bl + Al*Bh  (fp32 accumulate).
#define TSTRIDE 24   // smem row stride in bf16: 48B = 16B-aligned, conflict-distinct rows

__global__ __launch_bounds__(256, 2) void mma_xw1() {
    __shared__ __nv_bfloat16 sAh[128 * TSTRIDE];
    __shared__ __nv_bfloat16 sAl[128 * TSTRIDE];
    __shared__ __nv_bfloat16 sBh[128 * TSTRIDE];
    __shared__ __nv_bfloat16 sBl[128 * TSTRIDE];

    const int tid  = threadIdx.x;
    const int warp = tid >> 5;
    const int m0 = blockIdx.y * 128;
    const int n0 = blockIdx.x * 128;
    const int wm = (warp >> 2) * 64;     // warp m-offset within tile
    const int wn = (warp & 3) * 32;      // warp n-offset within tile

    wmma::fragment<wmma::accumulator, 16, 16, 16, float> acc[4][2];
#pragma unroll
    for (int i = 0; i < 4; ++i)
#pragma unroll
        for (int j = 0; j < 2; ++j) wmma::fill_fragment(acc[i][j], 0.0f);

    // gmem fill mapping: 2 threads per row, 8 bf16 (16B) each
    const int row = tid >> 1;
    const int ch  = (tid & 1) * 8;
    const __nv_bfloat16* gah = g_xh + (size_t)(m0 + row) * KPAD + ch;
    const __nv_bfloat16* gal = g_xl + (size_t)(m0 + row) * KPAD + ch;
    const __nv_bfloat16* gbh = g_wh + (size_t)(n0 + row) * KPAD + ch;
    const __nv_bfloat16* gbl = g_wl + (size_t)(n0 + row) * KPAD + ch;
    const int sdst = row * TSTRIDE + ch;

    uint4 pah = *(const uint4*)gah;
    uint4 pal = *(const uint4*)gal;
    uint4 pbh = *(const uint4*)gbh;
    uint4 pbl = *(const uint4*)gbl;

    for (int k0 = 0; k0 < DIN; k0 += 16) {
        *(uint4*)&sAh[sdst] = pah;
        *(uint4*)&sAl[sdst] = pal;
        *(uint4*)&sBh[sdst] = pbh;
        *(uint4*)&sBl[sdst] = pbl;
        __syncthreads();

        int kn = k0 + 16;
        if (kn < DIN) {
            pah = *(const uint4*)(gah + kn);
            pal = *(const uint4*)(gal + kn);
            pbh = *(const uint4*)(gbh + kn);
            pbl = *(const uint4*)(gbl + kn);
        }

        wmma::fragment<wmma::matrix_b, 16, 16, 16, __nv_bfloat16, wmma::col_major> bh[2], bl[2];
#pragma unroll
        for (int j = 0; j < 2; ++j) {
            wmma::load_matrix_sync(bh[j], &sBh[(wn + j * 16) * TSTRIDE], TSTRIDE);
            wmma::load_matrix_sync(bl[j], &sBl[(wn + j * 16) * TSTRIDE], TSTRIDE);
        }
#pragma unroll
        for (int i = 0; i < 4; ++i) {
            wmma::fragment<wmma::matrix_a, 16, 16, 16, __nv_bfloat16, wmma::row_major> ah, al;
            wmma::load_matrix_sync(ah, &sAh[(wm + i * 16) * TSTRIDE], TSTRIDE);
            wmma::load_matrix_sync(al, &sAl[(wm + i * 16) * TSTRIDE], TSTRIDE);
#pragma unroll
            for (int j = 0; j < 2; ++j) {
                wmma::mma_sync(acc[i][j], ah, bh[j], acc[i][j]);
                wmma::mma_sync(acc[i][j], ah, bl[j], acc[i][j]);
                wmma::mma_sync(acc[i][j], al, bh[j], acc[i][j]);
            }
        }
        __syncthreads();
    }

#pragma unroll
    for (int i = 0; i < 4; ++i)
#pragma unroll
        for (int j = 0; j < 2; ++j) {
            float* C = g_xW1 + (size_t)(m0 + wm + i * 16) * H + (n0 + wn + j * 16);
            wmma::store_matrix_sync(C, acc[i][j], H, wmma::mem_row_major);
        }
}

// ==================== Kernel 2: 50-step settle (unchanged from R3) ====================
__global__ __launch_bounds__(256, 2) void settle_kernel(
    const float* __restrict__ u1g, const float* __restrict__ u2g,
    const float* __restrict__ W2g, const float* __restrict__ b1g,
    const float* __restrict__ b2g, const int* __restrict__ steps_p,
    float* __restrict__ outg)
{
    __shared__ float c1_s[4 * H];
    __shared__ __align__(16) float r2_s[4][12];
    __shared__ u64 wpart[80 * 33];

    const int tid  = threadIdx.x;
    const int lane = tid & 31;
    const int wid  = tid >> 5;
    const int b0   = blockIdx.x * 4;
    const int nsteps = *steps_p;

    u64 w2p[4][5];
#pragma unroll
    for (int j = 0; j < 4; ++j) {
        const float* w = W2g + (tid + 256 * j) * DOUT;
#pragma unroll
        for (int k = 0; k < 5; ++k)
            w2p[j][k] = pk2(w[2 * k] * 0.0625f, w[2 * k + 1] * 0.0625f);
    }

    float u1v[4][4];
#pragma unroll
    for (int r = 0; r < 4; ++r)
#pragma unroll
        for (int j = 0; j < 4; ++j)
            u1v[r][j] = 0.5f * u1g[(size_t)(b0 + r) * H + tid + 256 * j];

    {
        const float4* xs = (const float4*)(g_xW1 + (size_t)b0 * H);
        const float4* bs = (const float4*)b1g;
        float4* dst = (float4*)c1_s;
#pragma unroll
        for (int i = 0; i < 4; ++i) {
            int e = tid + 256 * i;
            float4 xv = xs[e];
            float4 bv = bs[e & 255];
            dst[e] = make_float4(fmaf(0.03125f, xv.x, 0.0625f * bv.x),
                                 fmaf(0.03125f, xv.y, 0.0625f * bv.y),
                                 fmaf(0.03125f, xv.z, 0.0625f * bv.z),
                                 fmaf(0.03125f, xv.w, 0.0625f * bv.w));
        }
    }

    const bool pb = tid < 160;
    const int r_b  = tid / 40;
    const int rem  = tid - 40 * r_b;
    const int o_b  = rem >> 2;
    const int q4   = rem & 3;
    const int k_b  = o_b >> 1;
    const int half = o_b & 1;
    const float* fb = (const float*)(wpart + ((size_t)((r_b * 5 + k_b) * 4 + q4)) * 33);
    const float* fb_pre = (const float*)(wpart + ((size_t)(k_b * 4 + q4)) * 33);

    {
        u64 qa[5];
#pragma unroll
        for (int k = 0; k < 5; ++k)
            qa[k] = fadd2(fadd2(w2p[0][k], w2p[1][k]), fadd2(w2p[2][k], w2p[3][k]));
#pragma unroll
        for (int k = 0; k < 5; ++k)
            qa[k] = fadd2(qa[k], __shfl_xor_sync(0xffffffffu, qa[k], 16));
        if (lane < 16) {
            int pIdx = wid * 16 + lane;
            int chunk = pIdx >> 5, pos = pIdx & 31;
#pragma unroll
            for (int k = 0; k < 5; ++k)
                wpart[(k * 4 + chunk) * 33 + pos] = qa[k];
        }
    }
    __syncthreads();

    float C2v = 0.0f, wv = 0.0f, r2v = 0.0f;
    if (pb) {
        float s0a = 0, s0b = 0, s1a = 0, s1b = 0;
#pragma unroll
        for (int i = 0; i < 16; ++i) {
            float2 za = *(const float2*)(fb_pre + 4 * i);
            float2 zb = *(const float2*)(fb_pre + 4 * i + 2);
            s0a += za.x; s1a += za.y; s0b += zb.x; s1b += zb.y;
        }
        float s = half ? (s1a + s1b) : (s0a + s0b);
        s += __shfl_xor_sync(0xffffffffu, s, 1);
        s += __shfl_xor_sync(0xffffffffu, s, 2);
        C2v = fmaf(8.0f, s, b2g[o_b]);
        wv  = 0.5f * u2g[(b0 + r_b) * DOUT + o_b];
        float tau = tanh_(wv);
        r2v = fmaf(0.5f, tau, 0.5f);
        if (q4 == 0) r2_s[r_b][o_b] = r2v;
    }
    __syncthreads();

    for (int s = 0; s < nsteps; ++s) {
#pragma unroll
        for (int r = 0; r < 4; ++r) {
            ulonglong2 ra = *(const ulonglong2*)&r2_s[r][0];
            ulonglong2 rb = *(const ulonglong2*)&r2_s[r][4];
            u64 rc = *(const u64*)&r2_s[r][8];
            u64 r2p[5] = {ra.x, ra.y, rb.x, rb.y, rc};
            u64 qacc[5] = {0ULL, 0ULL, 0ULL, 0ULL, 0ULL};
#pragma unroll
            for (int j = 0; j < 4; ++j) {
                float v  = u1v[r][j];
                float th = tanh_(v);
                u64 p2 = fmul2(w2p[j][0], r2p[0]);
                p2 = ffma2(w2p[j][1], r2p[1], p2);
                p2 = ffma2(w2p[j][2], r2p[2], p2);
                p2 = ffma2(w2p[j][3], r2p[3], p2);
                p2 = ffma2(w2p[j][4], r2p[4], p2);
                float pa, pb2; upk2(p2, pa, pb2);
                u64 th2 = pk2(th, th);
#pragma unroll
                for (int k = 0; k < 5; ++k) qacc[k] = ffma2(th2, w2p[j][k], qacc[k]);
                float t   = (pa + pb2) + c1_s[r * H + tid + 256 * j];
                float omt = fmaf(-th, th, 1.0f);
                u1v[r][j] = fmaf(omt, t, 0.5f * v);
            }
#pragma unroll
            for (int k = 0; k < 5; ++k)
                qacc[k] = fadd2(qacc[k], __shfl_xor_sync(0xffffffffu, qacc[k], 16));
            if (lane < 16) {
                int pIdx = wid * 16 + lane;
                int chunk = pIdx >> 5, pos = pIdx & 31;
#pragma unroll
                for (int k = 0; k < 5; ++k)
                    wpart[((r * 5 + k) * 4 + chunk) * 33 + pos] = qacc[k];
            }
        }
        __syncthreads();

        if (pb) {
            float s0a = 0, s0b = 0, s1a = 0, s1b = 0;
#pragma unroll
            for (int i = 0; i < 16; ++i) {
                float2 za = *(const float2*)(fb + 4 * i);
                float2 zb = *(const float2*)(fb + 4 * i + 2);
                s0a += za.x; s1a += za.y; s0b += zb.x; s1b += zb.y;
            }
            float sv = half ? (s1a + s1b) : (s0a + s0b);
            sv += __shfl_xor_sync(0xffffffffu, sv, 1);
            sv += __shfl_xor_sync(0xffffffffu, sv, 2);
            float gq  = fmaf(8.0f, sv, C2v);
            float tau = tanh_(wv);
            float om  = fmaf(-tau, tau, 1.0f);
            wv = fmaf(0.0625f * om, gq, 0.5f * wv);
            r2v = fmaf(0.5f, tanh_(wv), 0.5f);
            if (q4 == 0) r2_s[r_b][o_b] = r2v;
        }
        __syncthreads();
    }

    if (pb && q4 == 0)
        outg[(b0 + r_b) * DOUT + o_b] = r2v;
}

// ==================== launch ====================
extern "C" void kernel_launch(void* const* d_in, const int* in_sizes, int n_in,
                              void* d_out, int out_size) {
    const float* x     = (const float*)d_in[0];
    const float* u1    = (const float*)d_in[1];
    const float* u2    = (const float*)d_in[2];
    const float* W1    = (const float*)d_in[3];
    const float* W2    = (const float*)d_in[4];
    const float* b1    = (const float*)d_in[5];
    const float* b2    = (const float*)d_in[6];
    const int*   steps = (const int*)d_in[7];
    float* out = (float*)d_out;

    const int B = in_sizes[1] / H;

    conv_x<<<(B * 208 + 255) / 256, 256>>>(x, B);
    conv_w1t<<<(H * KPAD + 255) / 256, 256>>>(W1);
    mma_xw1<<<dim3(H / 128, B / 128), 256>>>();
    settle_kernel<<<B / 4, 256>>>(u1, u2, W2, b1, b2, steps, out);
}